// round 11
// baseline (speedup 1.0000x reference)
#include <cuda_runtime.h>
#include <math.h>

#define B_   4
#define SX_  4096
#define SL_  256
#define D_   1024
#define H_   16
#define DH_  64
#define SKV_ (SX_ + SL_)   // 4352

// ---------------- scratch (device globals, no allocation) ----------------
__device__ float g_kvin[(size_t)B_ * SKV_ * D_];
__device__ float g_ln  [(size_t)B_ * SL_  * D_];
__device__ float g_q   [(size_t)B_ * SL_  * D_];
__device__ float g_kv  [(size_t)B_ * SKV_ * 2 * D_];
__device__ float g_y   [(size_t)B_ * SL_  * D_];
__device__ float g_wt  [(size_t)4 * 1024 * 1024];   // tf32-rounded Wq | Wkv | Wo

__device__ __forceinline__ unsigned f2tf32(float f) {
    unsigned r;
    asm("cvt.rna.tf32.f32 %0, %1;" : "=r"(r) : "f"(f));
    return r;
}
__device__ __forceinline__ float f2tf32f(float f) {
    return __uint_as_float(f2tf32(f));
}

__device__ __forceinline__ void mma_tf32(
    float& c0, float& c1, float& c2, float& c3,
    unsigned a0, unsigned a1, unsigned a2, unsigned a3,
    unsigned b0, unsigned b1)
{
    asm volatile(
        "mma.sync.aligned.m16n8k8.row.col.f32.tf32.tf32.f32 "
        "{%0,%1,%2,%3}, {%4,%5,%6,%7}, {%8,%9}, {%0,%1,%2,%3};"
        : "+f"(c0), "+f"(c1), "+f"(c2), "+f"(c3)
        : "r"(a0), "r"(a1), "r"(a2), "r"(a3), "r"(b0), "r"(b1));
}

__device__ __forceinline__ unsigned s2u(const void* p) {
    unsigned r;
    asm("{ .reg .u64 t; cvta.to.shared.u64 t, %1; cvt.u32.u64 %0, t; }"
        : "=r"(r) : "l"(p));
    return r;
}
__device__ __forceinline__ void cp16(unsigned dst, const void* src) {
    asm volatile("cp.async.ca.shared.global [%0], [%1], 16;" :: "r"(dst), "l"(src));
}
#define CP_COMMIT() asm volatile("cp.async.commit_group;" ::: "memory")
#define CP_WAIT1()  asm volatile("cp.async.wait_group 1;" ::: "memory")

// ---------------- tf32 rounding of all three weights, one launch ----------------
__global__ __launch_bounds__(256) void cvt3_kernel(
    const float* __restrict__ wq, const float* __restrict__ wkv,
    const float* __restrict__ wo, float* __restrict__ out)
{
    int blk = blockIdx.x;
    const float* src;
    float* dst;
    if (blk < 1024)      { src = wq  + (size_t)blk * 1024;          dst = out + (size_t)blk * 1024; }
    else if (blk < 3072) { src = wkv + (size_t)(blk - 1024) * 1024; dst = out + (size_t)blk * 1024; }
    else                 { src = wo  + (size_t)(blk - 3072) * 1024; dst = out + (size_t)blk * 1024; }
    int i = threadIdx.x * 4;
    float4 v = *(const float4*)(src + i);
    v.x = f2tf32f(v.x); v.y = f2tf32f(v.y);
    v.z = f2tf32f(v.z); v.w = f2tf32f(v.w);
    *(float4*)(dst + i) = v;
}

// ---------------- cp.async 3-stage tensor GEMM ----------------
// C[m][n] = sum_k A[m][k]*B[k][n]. A,B pre-rounded to tf32 values.
// CTA tile 128 x TN, 256 threads, 8 warps (2 x 4), warp tile 64 x (TN/4),
// k-tile 16, 3 stages.  TN=256: warp tile 64x64 (1 CTA/SM); TN=64: small GEMMs.
#define AST 20

template<int TN>
__global__ __launch_bounds__(256, TN == 256 ? 1 : 2) void tgemm_ca(
    const float* __restrict__ A, int lda,
    const float* __restrict__ Bm, int ldb,
    float* __restrict__ C, int ldc)
{
    constexpr int BST  = TN + 8;
    constexpr int STGF = 128 * AST + 16 * BST;
    constexpr int NI   = TN / 32;

    extern __shared__ float smf[];
    unsigned sbase = s2u(smf);

    int tid  = threadIdx.x;
    int lane = tid & 31, warp = tid >> 5;
    int wm = (warp & 1) * 64;
    int wn = (warp >> 1) * (TN / 4);
    int tig = lane & 3;
    int grp = lane >> 2;
    int row0 = blockIdx.y * 128, col0 = blockIdx.x * TN;

    const float* Ag = A  + (size_t)row0 * lda;
    const float* Bg = Bm + col0;

    auto issueA = [&](int stage, int k0) {
        unsigned dst0 = sbase + (unsigned)(stage * STGF) * 4u;
#pragma unroll
        for (int j = 0; j < 2; j++) {
            int c = tid + 256 * j;
            int r = c >> 2, q = c & 3;
            cp16(dst0 + (unsigned)(r * AST + q * 4) * 4u,
                 Ag + (size_t)r * lda + k0 + q * 4);
        }
    };
    auto issueB = [&](int stage, int k0) {
        unsigned dst0 = sbase + (unsigned)(stage * STGF + 128 * AST) * 4u;
        if (TN == 256) {       // 1024 chunks, 4 per thread
#pragma unroll
            for (int j = 0; j < 4; j++) {
                int c = tid + 256 * j;
                int kr = c >> 6, nb = c & 63;
                cp16(dst0 + (unsigned)(kr * BST + nb * 4) * 4u,
                     Bg + (size_t)(k0 + kr) * ldb + nb * 4);
            }
        } else if (TN == 128) {
#pragma unroll
            for (int j = 0; j < 2; j++) {
                int c = tid + 256 * j;
                int kr = c >> 5, nb = c & 31;
                cp16(dst0 + (unsigned)(kr * BST + nb * 4) * 4u,
                     Bg + (size_t)(k0 + kr) * ldb + nb * 4);
            }
        } else {               // TN == 64: 256 chunks, 1 per thread
            int kr = tid >> 4, nb = tid & 15;
            cp16(dst0 + (unsigned)(kr * BST + nb * 4) * 4u,
                 Bg + (size_t)(k0 + kr) * ldb + nb * 4);
        }
    };

    float acc[4][NI][4];
#pragma unroll
    for (int i = 0; i < 4; i++)
#pragma unroll
        for (int j = 0; j < NI; j++)
#pragma unroll
            for (int t = 0; t < 4; t++) acc[i][j][t] = 0.f;

    // prologue: stages 0,1
    issueA(0, 0);  issueB(0, 0);  CP_COMMIT();
    issueA(1, 16); issueB(1, 16); CP_COMMIT();

    const int NIT = 64;   // K=1024 / 16
    for (int it = 0; it < NIT; ++it) {
        CP_WAIT1();
        __syncthreads();

        if (it + 2 < NIT) {
            int st = (it + 2) % 3;
            issueA(st, (it + 2) * 16);
            issueB(st, (it + 2) * 16);
        }
        CP_COMMIT();

        const float* As = smf + (it % 3) * STGF;
        const float* Bs = As + 128 * AST;
#pragma unroll
        for (int ks = 0; ks < 2; ks++) {
            int kb = ks * 8;
            unsigned af[4][4], bf[NI][2];
#pragma unroll
            for (int mi = 0; mi < 4; mi++) {
                int r = wm + mi * 16 + grp;
                af[mi][0] = __float_as_uint(As[r * AST + kb + tig]);
                af[mi][1] = __float_as_uint(As[(r + 8) * AST + kb + tig]);
                af[mi][2] = __float_as_uint(As[r * AST + kb + tig + 4]);
                af[mi][3] = __float_as_uint(As[(r + 8) * AST + kb + tig + 4]);
            }
#pragma unroll
            for (int ni = 0; ni < NI; ni++) {
                int n = wn + ni * 8 + grp;
                bf[ni][0] = __float_as_uint(Bs[(kb + tig) * BST + n]);
                bf[ni][1] = __float_as_uint(Bs[(kb + tig + 4) * BST + n]);
            }
#pragma unroll
            for (int mi = 0; mi < 4; mi++)
#pragma unroll
                for (int ni = 0; ni < NI; ni++)
                    mma_tf32(acc[mi][ni][0], acc[mi][ni][1], acc[mi][ni][2], acc[mi][ni][3],
                             af[mi][0], af[mi][1], af[mi][2], af[mi][3],
                             bf[ni][0], bf[ni][1]);
        }
    }

#pragma unroll
    for (int mi = 0; mi < 4; mi++) {
#pragma unroll
        for (int ni = 0; ni < NI; ni++) {
            int row = row0 + wm + mi * 16 + grp;
            int col = col0 + wn + ni * 8 + tig * 2;
            *(float2*)&C[(size_t)row * ldc + col] =
                make_float2(acc[mi][ni][0], acc[mi][ni][1]);
            *(float2*)&C[(size_t)(row + 8) * ldc + col] =
                make_float2(acc[mi][ni][2], acc[mi][ni][3]);
        }
    }
}

// ---------------- LayerNorm (tf32-rounded outputs) ----------------
__global__ __launch_bounds__(256) void ln_kernel(
    const float* __restrict__ x, const float* __restrict__ g,
    const float* __restrict__ bta, float* __restrict__ dst1,
    float* __restrict__ dst2, int rowsPerBatch, int rowOff)
{
    int r = blockIdx.x;
    int tid = threadIdx.x;
    const float* xr = x + (size_t)r * D_;

    float v[4], s = 0.f, s2 = 0.f;
#pragma unroll
    for (int i = 0; i < 4; i++) {
        v[i] = xr[tid + i * 256];
        s += v[i];
        s2 += v[i] * v[i];
    }
#pragma unroll
    for (int o = 16; o > 0; o >>= 1) {
        s  += __shfl_xor_sync(0xffffffffu, s,  o);
        s2 += __shfl_xor_sync(0xffffffffu, s2, o);
    }
    __shared__ float ss[8], ss2[8];
    int w = tid >> 5, l = tid & 31;
    if (l == 0) { ss[w] = s; ss2[w] = s2; }
    __syncthreads();
    if (tid == 0) {
        float a = 0.f, b2 = 0.f;
#pragma unroll
        for (int i = 0; i < 8; i++) { a += ss[i]; b2 += ss2[i]; }
        float mu = a * (1.f / D_);
        ss[0]  = mu;
        ss2[0] = b2 * (1.f / D_) - mu * mu;
    }
    __syncthreads();
    float mu = ss[0];
    float inv = rsqrtf(ss2[0] + 1e-5f);

    size_t drow = ((size_t)(r / rowsPerBatch) * SKV_ + (r % rowsPerBatch) + rowOff) * D_;
#pragma unroll
    for (int i = 0; i < 4; i++) {
        int c = tid + i * 256;
        float o = f2tf32f((v[i] - mu) * inv * g[c] + bta[c]);
        dst1[drow + c] = o;
        if (dst2) dst2[(size_t)r * D_ + c] = o;
    }
}

// ---------------- per-head RMSNorm (warp per 64-wide chunk) — k only ---------
__global__ __launch_bounds__(256) void rms_kernel(
    float* __restrict__ p, const float* __restrict__ gamma,
    int rowStride, long long totalChunks, float outscale)
{
    long long chunk = (long long)blockIdx.x * 8 + (threadIdx.x >> 5);
    if (chunk >= totalChunks) return;
    int lane = threadIdx.x & 31;
    long long row = chunk / H_;
    int h = (int)(chunk % H_);
    float* base = p + row * (size_t)rowStride + h * DH_;

    float v0 = base[lane];
    float v1 = base[lane + 32];
    float ss = v0 * v0 + v1 * v1;
#pragma unroll
    for (int o = 16; o > 0; o >>= 1) ss += __shfl_xor_sync(0xffffffffu, ss, o);
    float norm = sqrtf(ss) * 0.125f;
    float scale = outscale / fmaxf(norm, 1e-8f);
    base[lane]      = v0 * scale * gamma[lane];
    base[lane + 32] = v1 * scale * gamma[lane + 32];
}

// ---------------- fused flash attention (q-RMSNorm fused in staging) ---------
#define KSS 68
#define VSS 72
#define PSS 76

__global__ __launch_bounds__(256) void flash_kernel(
    const float* __restrict__ qb, const float* __restrict__ kvb,
    const float* __restrict__ mask_x, const float* __restrict__ mask_l,
    const float* __restrict__ qk_g, float* __restrict__ y)
{
    extern __shared__ float sm[];
    float* Ks = sm;
    float* Vs = Ks + 64 * KSS;
    float* Ps = Vs + 64 * VSS;
    float* Ms = Ps + 128 * PSS;

    const float NEGMIN = -3.4028234663852886e38f;
    int tid = threadIdx.x;
    int lane = tid & 31, warp = tid >> 5;
    int grp = lane >> 2, tig = lane & 3;
    int b = blockIdx.y >> 4, h = blockIdx.y & 15;
    int q0 = blockIdx.x * 128;
    int r0 = warp * 16 + grp;

    int sr = tid >> 4, c4 = (tid & 15) * 4;
    float4 g4 = *(const float4*)(qk_g + c4);

    // stage Q tile -> Ps with fused RMSNorm (x 0.125 score scale)
    const float* Qg = qb + ((size_t)b * SL_ + q0) * D_ + h * DH_;
#pragma unroll
    for (int p = 0; p < 8; p++) {
        float4 v = *(const float4*)(Qg + (size_t)(p * 16 + sr) * D_ + c4);
        float ss = v.x * v.x + v.y * v.y + v.z * v.z + v.w * v.w;
        ss += __shfl_xor_sync(0xffffffffu, ss, 1);
        ss += __shfl_xor_sync(0xffffffffu, ss, 2);
        ss += __shfl_xor_sync(0xffffffffu, ss, 4);
        ss += __shfl_xor_sync(0xffffffffu, ss, 8);
        float norm = sqrtf(ss) * 0.125f;
        float sc = 0.125f / fmaxf(norm, 1e-8f);
        v.x *= sc * g4.x; v.y *= sc * g4.y;
        v.z *= sc * g4.z; v.w *= sc * g4.w;
        *(float4*)(Ps + (p * 16 + sr) * PSS + c4) = v;
    }
    __syncthreads();

    unsigned qf[8][4];
#pragma unroll
    for (int c = 0; c < 8; c++) {
        qf[c][0] = f2tf32(Ps[r0 * PSS + c * 8 + tig]);
        qf[c][1] = f2tf32(Ps[(r0 + 8) * PSS + c * 8 + tig]);
        qf[c][2] = f2tf32(Ps[r0 * PSS + c * 8 + tig + 4]);
        qf[c][3] = f2tf32(Ps[(r0 + 8) * PSS + c * 8 + tig + 4]);
    }
    float mlq0 = mask_l[b * SL_ + q0 + r0];
    float mlq1 = mask_l[b * SL_ + q0 + r0 + 8];

    float m0 = -INFINITY, m1 = -INFINITY, l0 = 0.f, l1 = 0.f;
    float o[8][4];
#pragma unroll
    for (int i = 0; i < 8; i++)
#pragma unroll
        for (int j = 0; j < 4; j++) o[i][j] = 0.f;

    const float* Kg = kvb + (size_t)b * SKV_ * (2 * D_) + h * DH_;

    for (int kt = 0; kt < SKV_ / 64; kt++) {
        __syncthreads();
#pragma unroll
        for (int p = 0; p < 4; p++) {
            const float* src = Kg + (size_t)(kt * 64 + p * 16 + sr) * (2 * D_) + c4;
            float4 kvv = *(const float4*)src;
            float4 vvv = *(const float4*)(src + D_);
            kvv.x = f2tf32f(kvv.x); kvv.y = f2tf32f(kvv.y);
            kvv.z = f2tf32f(kvv.z); kvv.w = f2tf32f(kvv.w);
            vvv.x = f2tf32f(vvv.x); vvv.y = f2tf32f(vvv.y);
            vvv.z = f2tf32f(vvv.z); vvv.w = f2tf32f(vvv.w);
            *(float4*)(Ks + (p * 16 + sr) * KSS + c4) = kvv;
            *(float4*)(Vs + (p * 16 + sr) * VSS + c4) = vvv;
        }
        if (tid < 64) {
            int t = kt * 64 + tid;
            Ms[tid] = (t < SX_) ? mask_x[b * SX_ + t] : mask_l[b * SL_ + t - SX_];
        }
        __syncthreads();

        float s[8][4];
#pragma unroll
        for (int i = 0; i < 8; i++) { s[i][0] = s[i][1] = s[i][2] = s[i][3] = 0.f; }
#pragma unroll
        for (int c = 0; c < 8; c++) {
#pragma unroll
            for (int ni = 0; ni < 8; ni++) {
                unsigned kb0 = __float_as_uint(Ks[(ni * 8 + grp) * KSS + c * 8 + tig]);
                unsigned kb1 = __float_as_uint(Ks[(ni * 8 + grp) * KSS + c * 8 + tig + 4]);
                mma_tf32(s[ni][0], s[ni][1], s[ni][2], s[ni][3],
                         qf[c][0], qf[c][1], qf[c][2], qf[c][3], kb0, kb1);
            }
        }

        float mx0 = m0, mx1 = m1;
#pragma unroll
        for (int ni = 0; ni < 8; ni++) {
            float mk0 = Ms[ni * 8 + tig * 2], mk1 = Ms[ni * 8 + tig * 2 + 1];
            s[ni][0] += (1.f - mk0 * mlq0) * NEGMIN;
            s[ni][1] += (1.f - mk1 * mlq0) * NEGMIN;
            s[ni][2] += (1.f - mk0 * mlq1) * NEGMIN;
            s[ni][3] += (1.f - mk1 * mlq1) * NEGMIN;
            mx0 = fmaxf(mx0, fmaxf(s[ni][0], s[ni][1]));
            mx1 = fmaxf(mx1, fmaxf(s[ni][2], s[ni][3]));
        }
        mx0 = fmaxf(mx0, __shfl_xor_sync(0xffffffffu, mx0, 1));
        mx0 = fmaxf(mx0, __shfl_xor_sync(0xffffffffu, mx0, 2));
        mx1 = fmaxf(mx1, __shfl_xor_sync(0xffffffffu, mx1, 1));
        mx1 = fmaxf(mx1, __shfl_xor_sync(0xffffffffu, mx1, 2));
        float sc0 = expf(m0 - mx0);
        float sc1 = expf(m1 - mx1);
        m0 = mx0; m1 = mx1;
        float rs0 = 0.f, rs1 = 0.f;
#pragma unroll
        for (int ni = 0; ni < 8; ni++) {
            float p0 = expf(s[ni][0] - m0), p1 = expf(s[ni][1] - m0);
            float p2 = expf(s[ni][2] - m1), p3 = expf(s[ni][3] - m1);
            rs0 += p0 + p1; rs1 += p2 + p3;
            *(float2*)(Ps + r0 * PSS + ni * 8 + tig * 2) =
                make_float2(f2tf32f(p0), f2tf32f(p1));
            *(float2*)(Ps + (r0 + 8) * PSS + ni * 8 + tig * 2) =
                make_float2(f2tf32f(p2), f2tf32f(p3));
        }
        rs0 += __shfl_xor_sync(0xffffffffu, rs0, 1);
        rs0 += __shfl_xor_sync(0xffffffffu, rs0, 2);
        rs1 += __shfl_xor_sync(0xffffffffu, rs1, 1);
        rs1 += __shfl_xor_sync(0xffffffffu, rs1, 2);
        l0 = l0 * sc0 + rs0;
        l1 = l1 * sc1 + rs1;
#pragma unroll
        for (int ni = 0; ni < 8; ni++) {
            o[ni][0] *= sc0; o[ni][1] *= sc0;
            o[ni][2] *= sc1; o[ni][3] *= sc1;
        }
        __syncwarp();

#pragma unroll
        for (int c = 0; c < 8; c++) {
            unsigned pf0 = __float_as_uint(Ps[r0 * PSS + c * 8 + tig]);
            unsigned pf1 = __float_as_uint(Ps[(r0 + 8) * PSS + c * 8 + tig]);
            unsigned pf2 = __float_as_uint(Ps[r0 * PSS + c * 8 + tig + 4]);
            unsigned pf3 = __float_as_uint(Ps[(r0 + 8) * PSS + c * 8 + tig + 4]);
#pragma unroll
            for (int ni = 0; ni < 8; ni++) {
                unsigned vb0 = __float_as_uint(Vs[(c * 8 + tig) * VSS + ni * 8 + grp]);
                unsigned vb1 = __float_as_uint(Vs[(c * 8 + tig + 4) * VSS + ni * 8 + grp]);
                mma_tf32(o[ni][0], o[ni][1], o[ni][2], o[ni][3],
                         pf0, pf1, pf2, pf3, vb0, vb1);
            }
        }
    }

    // y rounded to tf32 (consumed by the out-projection GEMM)
    float inv0 = 1.f / l0, inv1 = 1.f / l1;
    float* yg = y + ((size_t)b * SL_ + q0 + r0) * D_ + h * DH_;
#pragma unroll
    for (int ni = 0; ni < 8; ni++) {
        *(float2*)(yg + ni * 8 + tig * 2) =
            make_float2(f2tf32f(o[ni][0] * inv0), f2tf32f(o[ni][1] * inv0));
        *(float2*)(yg + (size_t)8 * D_ + ni * 8 + tig * 2) =
            make_float2(f2tf32f(o[ni][2] * inv1), f2tf32f(o[ni][3] * inv1));
    }
}

// ---------------- launch ----------------
extern "C" void kernel_launch(void* const* d_in, const int* in_sizes, int n_in,
                              void* d_out, int out_size)
{
    const float* x       = (const float*)d_in[0];
    const float* latents = (const float*)d_in[1];
    const float* mask_x  = (const float*)d_in[2];
    const float* mask_l  = (const float*)d_in[3];
    const float* ln_x_g  = (const float*)d_in[4];
    const float* ln_x_b  = (const float*)d_in[5];
    const float* ln_l_g  = (const float*)d_in[6];
    const float* ln_l_b  = (const float*)d_in[7];
    const float* Wq      = (const float*)d_in[8];
    const float* Wkv     = (const float*)d_in[9];
    const float* qk_g    = (const float*)d_in[10];
    const float* Wo      = (const float*)d_in[11];
    float* out = (float*)d_out;

    float *kvin, *lnb, *qb, *kvb, *yb, *wt;
    cudaGetSymbolAddress((void**)&kvin, g_kvin);
    cudaGetSymbolAddress((void**)&lnb,  g_ln);
    cudaGetSymbolAddress((void**)&qb,   g_q);
    cudaGetSymbolAddress((void**)&kvb,  g_kv);
    cudaGetSymbolAddress((void**)&yb,   g_y);
    cudaGetSymbolAddress((void**)&wt,   g_wt);
    float* wq32  = wt;
    float* wkv32 = wt + (size_t)1024 * 1024;
    float* wo32  = wt + (size_t)3 * 1024 * 1024;

    int flash_smem   = (64 * KSS + 64 * VSS + 128 * PSS + 64) * 4;
    int gemm_smem256 = 3 * (128 * AST + 16 * (256 + 8)) * 4;   // 81408
    int gemm_smem64  = 3 * (128 * AST + 16 * (64 + 8)) * 4;    // 44544
    static int smem_set = 0;
    if (!smem_set) {
        cudaFuncSetAttribute(flash_kernel,
                             cudaFuncAttributeMaxDynamicSharedMemorySize, flash_smem);
        cudaFuncSetAttribute(tgemm_ca<256>,
                             cudaFuncAttributeMaxDynamicSharedMemorySize, gemm_smem256);
        cudaFuncSetAttribute(tgemm_ca<64>,
                             cudaFuncAttributeMaxDynamicSharedMemorySize, gemm_smem64);
        smem_set = 1;
    }

    // 0) round all weights to tf32 (one launch)
    cvt3_kernel<<<4096, 256>>>(Wq, Wkv, Wo, wq32);

    // 1) LayerNorms -> kvin (concat) and lnb, tf32-rounded
    ln_kernel<<<B_ * SX_, 256>>>(x, ln_x_g, ln_x_b, kvin, nullptr, SX_, 0);
    ln_kernel<<<B_ * SL_, 256>>>(latents, ln_l_g, ln_l_b, kvin, lnb, SL_, SX_);

    // 2) q = ln @ Wq   (TN=64 -> 128 CTAs)
    tgemm_ca<64><<<dim3(16, 8), 256, gemm_smem64>>>(lnb, D_, wq32, D_, qb, D_);

    // 3) kv = kvin @ Wkv   (TN=256: warp tile 64x64)
    tgemm_ca<256><<<dim3(8, 136), 256, gemm_smem256>>>(kvin, D_, wkv32, 2 * D_, kvb, 2 * D_);

    // 4) k RMSNorm (q rms fused into flash)
    rms_kernel<<<(B_ * SKV_ * H_) / 8, 256>>>(kvb, qk_g, 2 * D_, (long long)B_ * SKV_ * H_, 1.0f);

    // 5) fused attention (q RMSNorm + 0.125 scale inside) -> y (tf32-rounded)
    flash_kernel<<<dim3(SL_ / 128, B_ * H_), 256, flash_smem>>>(
        qb, kvb, mask_x, mask_l, qk_g, yb);

    // 6) out = y @ Wo   (TN=64 -> 128 CTAs)
    tgemm_ca<64><<<dim3(16, 8), 256, gemm_smem64>>>(yb, D_, wo32, D_, out, D_);
}

// round 12
// speedup vs baseline: 1.0271x; 1.0271x over previous
#include <cuda_runtime.h>
#include <math.h>

#define B_   4
#define SX_  4096
#define SL_  256
#define D_   1024
#define H_   16
#define DH_  64
#define SKV_ (SX_ + SL_)   // 4352

// ---------------- scratch (device globals, no allocation) ----------------
__device__ float g_kvin[(size_t)B_ * SKV_ * D_];
__device__ float g_ln  [(size_t)B_ * SL_  * D_];
__device__ float g_q   [(size_t)B_ * SL_  * D_];
__device__ float g_kv  [(size_t)B_ * SKV_ * 2 * D_];
__device__ float g_y   [(size_t)B_ * SL_  * D_];
__device__ float g_wt  [(size_t)4 * 1024 * 1024];      // tf32-rounded Wq | Wkv | Wo
__device__ float g_ks  [(size_t)B_ * SKV_ * H_];        // k rms scales (1.1 MB)

__device__ __forceinline__ unsigned f2tf32(float f) {
    unsigned r;
    asm("cvt.rna.tf32.f32 %0, %1;" : "=r"(r) : "f"(f));
    return r;
}
__device__ __forceinline__ float f2tf32f(float f) {
    return __uint_as_float(f2tf32(f));
}

__device__ __forceinline__ void mma_tf32(
    float& c0, float& c1, float& c2, float& c3,
    unsigned a0, unsigned a1, unsigned a2, unsigned a3,
    unsigned b0, unsigned b1)
{
    asm volatile(
        "mma.sync.aligned.m16n8k8.row.col.f32.tf32.tf32.f32 "
        "{%0,%1,%2,%3}, {%4,%5,%6,%7}, {%8,%9}, {%0,%1,%2,%3};"
        : "+f"(c0), "+f"(c1), "+f"(c2), "+f"(c3)
        : "r"(a0), "r"(a1), "r"(a2), "r"(a3), "r"(b0), "r"(b1));
}

__device__ __forceinline__ unsigned s2u(const void* p) {
    unsigned r;
    asm("{ .reg .u64 t; cvta.to.shared.u64 t, %1; cvt.u32.u64 %0, t; }"
        : "=r"(r) : "l"(p));
    return r;
}
__device__ __forceinline__ void cp16(unsigned dst, const void* src) {
    asm volatile("cp.async.ca.shared.global [%0], [%1], 16;" :: "r"(dst), "l"(src));
}
#define CP_COMMIT() asm volatile("cp.async.commit_group;" ::: "memory")
#define CP_WAIT1()  asm volatile("cp.async.wait_group 1;" ::: "memory")

// ---------------- tf32 rounding of all three weights, one launch ----------------
__global__ __launch_bounds__(256) void cvt3_kernel(
    const float* __restrict__ wq, const float* __restrict__ wkv,
    const float* __restrict__ wo, float* __restrict__ out)
{
    int blk = blockIdx.x;
    const float* src;
    float* dst;
    if (blk < 1024)      { src = wq  + (size_t)blk * 1024;          dst = out + (size_t)blk * 1024; }
    else if (blk < 3072) { src = wkv + (size_t)(blk - 1024) * 1024; dst = out + (size_t)blk * 1024; }
    else                 { src = wo  + (size_t)(blk - 3072) * 1024; dst = out + (size_t)blk * 1024; }
    int i = threadIdx.x * 4;
    float4 v = *(const float4*)(src + i);
    v.x = f2tf32f(v.x); v.y = f2tf32f(v.y);
    v.z = f2tf32f(v.z); v.w = f2tf32f(v.w);
    *(float4*)(dst + i) = v;
}

// ---------------- cp.async 3-stage tensor GEMM (round-10 proven core) --------
#define AST 20

template<int TN>
__global__ __launch_bounds__(256, 2) void tgemm_ca(
    const float* __restrict__ A, int lda,
    const float* __restrict__ Bm, int ldb,
    float* __restrict__ C, int ldc)
{
    constexpr int BST  = TN + 8;
    constexpr int STGF = 128 * AST + 16 * BST;
    constexpr int NI   = TN / 32;

    extern __shared__ float smf[];
    unsigned sbase = s2u(smf);

    int tid  = threadIdx.x;
    int lane = tid & 31, warp = tid >> 5;
    int wm = (warp & 1) * 64;
    int wn = (warp >> 1) * (TN / 4);
    int tig = lane & 3;
    int grp = lane >> 2;
    int row0 = blockIdx.y * 128, col0 = blockIdx.x * TN;

    const float* Ag = A  + (size_t)row0 * lda;
    const float* Bg = Bm + col0;

    auto issueA = [&](int stage, int k0) {
        unsigned dst0 = sbase + (unsigned)(stage * STGF) * 4u;
#pragma unroll
        for (int j = 0; j < 2; j++) {
            int c = tid + 256 * j;
            int r = c >> 2, q = c & 3;
            cp16(dst0 + (unsigned)(r * AST + q * 4) * 4u,
                 Ag + (size_t)r * lda + k0 + q * 4);
        }
    };
    auto issueB = [&](int stage, int k0) {
        unsigned dst0 = sbase + (unsigned)(stage * STGF + 128 * AST) * 4u;
        if (TN == 128) {
#pragma unroll
            for (int j = 0; j < 2; j++) {
                int c = tid + 256 * j;
                int kr = c >> 5, nb = c & 31;
                cp16(dst0 + (unsigned)(kr * BST + nb * 4) * 4u,
                     Bg + (size_t)(k0 + kr) * ldb + nb * 4);
            }
        } else {   // TN == 64: 256 chunks, 1 per thread
            int kr = tid >> 4, nb = tid & 15;
            cp16(dst0 + (unsigned)(kr * BST + nb * 4) * 4u,
                 Bg + (size_t)(k0 + kr) * ldb + nb * 4);
        }
    };

    float acc[4][NI][4];
#pragma unroll
    for (int i = 0; i < 4; i++)
#pragma unroll
        for (int j = 0; j < NI; j++)
#pragma unroll
            for (int t = 0; t < 4; t++) acc[i][j][t] = 0.f;

    // prologue: stages 0,1
    issueA(0, 0);  issueB(0, 0);  CP_COMMIT();
    issueA(1, 16); issueB(1, 16); CP_COMMIT();

    const int NIT = 64;   // K=1024 / 16
    for (int it = 0; it < NIT; ++it) {
        CP_WAIT1();
        __syncthreads();

        if (it + 2 < NIT) {
            int st = (it + 2) % 3;
            issueA(st, (it + 2) * 16);
            issueB(st, (it + 2) * 16);
        }
        CP_COMMIT();

        const float* As = smf + (it % 3) * STGF;
        const float* Bs = As + 128 * AST;
#pragma unroll
        for (int ks = 0; ks < 2; ks++) {
            int kb = ks * 8;
            unsigned af[4][4], bf[NI][2];
#pragma unroll
            for (int mi = 0; mi < 4; mi++) {
                int r = wm + mi * 16 + grp;
                af[mi][0] = __float_as_uint(As[r * AST + kb + tig]);
                af[mi][1] = __float_as_uint(As[(r + 8) * AST + kb + tig]);
                af[mi][2] = __float_as_uint(As[r * AST + kb + tig + 4]);
                af[mi][3] = __float_as_uint(As[(r + 8) * AST + kb + tig + 4]);
            }
#pragma unroll
            for (int ni = 0; ni < NI; ni++) {
                int n = wn + ni * 8 + grp;
                bf[ni][0] = __float_as_uint(Bs[(kb + tig) * BST + n]);
                bf[ni][1] = __float_as_uint(Bs[(kb + tig + 4) * BST + n]);
            }
#pragma unroll
            for (int mi = 0; mi < 4; mi++)
#pragma unroll
                for (int ni = 0; ni < NI; ni++)
                    mma_tf32(acc[mi][ni][0], acc[mi][ni][1], acc[mi][ni][2], acc[mi][ni][3],
                             af[mi][0], af[mi][1], af[mi][2], af[mi][3],
                             bf[ni][0], bf[ni][1]);
        }
    }

#pragma unroll
    for (int mi = 0; mi < 4; mi++) {
#pragma unroll
        for (int ni = 0; ni < NI; ni++) {
            int row = row0 + wm + mi * 16 + grp;
            int col = col0 + wn + ni * 8 + tig * 2;
            *(float2*)&C[(size_t)row * ldc + col] =
                make_float2(acc[mi][ni][0], acc[mi][ni][1]);
            *(float2*)&C[(size_t)(row + 8) * ldc + col] =
                make_float2(acc[mi][ni][2], acc[mi][ni][3]);
        }
    }
}

// ---------------- LayerNorm (tf32-rounded outputs) ----------------
__global__ __launch_bounds__(256) void ln_kernel(
    const float* __restrict__ x, const float* __restrict__ g,
    const float* __restrict__ bta, float* __restrict__ dst1,
    float* __restrict__ dst2, int rowsPerBatch, int rowOff)
{
    int r = blockIdx.x;
    int tid = threadIdx.x;
    const float* xr = x + (size_t)r * D_;

    float v[4], s = 0.f, s2 = 0.f;
#pragma unroll
    for (int i = 0; i < 4; i++) {
        v[i] = xr[tid + i * 256];
        s += v[i];
        s2 += v[i] * v[i];
    }
#pragma unroll
    for (int o = 16; o > 0; o >>= 1) {
        s  += __shfl_xor_sync(0xffffffffu, s,  o);
        s2 += __shfl_xor_sync(0xffffffffu, s2, o);
    }
    __shared__ float ss[8], ss2[8];
    int w = tid >> 5, l = tid & 31;
    if (l == 0) { ss[w] = s; ss2[w] = s2; }
    __syncthreads();
    if (tid == 0) {
        float a = 0.f, b2 = 0.f;
#pragma unroll
        for (int i = 0; i < 8; i++) { a += ss[i]; b2 += ss2[i]; }
        float mu = a * (1.f / D_);
        ss[0]  = mu;
        ss2[0] = b2 * (1.f / D_) - mu * mu;
    }
    __syncthreads();
    float mu = ss[0];
    float inv = rsqrtf(ss2[0] + 1e-5f);

    size_t drow = ((size_t)(r / rowsPerBatch) * SKV_ + (r % rowsPerBatch) + rowOff) * D_;
#pragma unroll
    for (int i = 0; i < 4; i++) {
        int c = tid + i * 256;
        float o = f2tf32f((v[i] - mu) * inv * g[c] + bta[c]);
        dst1[drow + c] = o;
        if (dst2) dst2[(size_t)r * D_ + c] = o;
    }
}

// ---------------- k RMS scale pass (read-only) ----------------
// scales[(b*SKV + t)*H + h] = 1 / max(||k_row_head|| * DH^-0.5, eps)
__global__ __launch_bounds__(256) void kscale_kernel(
    const float* __restrict__ kv, float* __restrict__ scales)
{
    long long chunk = (long long)blockIdx.x * 8 + (threadIdx.x >> 5);
    int lane = threadIdx.x & 31;
    long long row = chunk / H_;
    int h = (int)(chunk % H_);
    const float* base = kv + row * (size_t)(2 * D_) + h * DH_;

    float v0 = base[lane];
    float v1 = base[lane + 32];
    float ss = v0 * v0 + v1 * v1;
#pragma unroll
    for (int o = 16; o > 0; o >>= 1) ss += __shfl_xor_sync(0xffffffffu, ss, o);
    if (lane == 0) {
        float norm = sqrtf(ss) * 0.125f;
        scales[chunk] = 1.f / fmaxf(norm, 1e-8f);
    }
}

// ---------------- fused flash attention (q-RMS fused; k scale applied) -------
#define KSS 68
#define VSS 72
#define PSS 76

__global__ __launch_bounds__(256) void flash_kernel(
    const float* __restrict__ qb, const float* __restrict__ kvb,
    const float* __restrict__ mask_x, const float* __restrict__ mask_l,
    const float* __restrict__ qk_g, const float* __restrict__ kscl,
    float* __restrict__ y)
{
    extern __shared__ float sm[];
    float* Ks = sm;
    float* Vs = Ks + 64 * KSS;
    float* Ps = Vs + 64 * VSS;
    float* Ms = Ps + 128 * PSS;

    const float NEGMIN = -3.4028234663852886e38f;
    int tid = threadIdx.x;
    int lane = tid & 31, warp = tid >> 5;
    int grp = lane >> 2, tig = lane & 3;
    int b = blockIdx.y >> 4, h = blockIdx.y & 15;
    int q0 = blockIdx.x * 128;
    int r0 = warp * 16 + grp;

    int sr = tid >> 4, c4 = (tid & 15) * 4;
    float4 g4 = *(const float4*)(qk_g + c4);

    // stage Q tile -> Ps with fused RMSNorm (x 0.125 score scale)
    const float* Qg = qb + ((size_t)b * SL_ + q0) * D_ + h * DH_;
#pragma unroll
    for (int p = 0; p < 8; p++) {
        float4 v = *(const float4*)(Qg + (size_t)(p * 16 + sr) * D_ + c4);
        float ss = v.x * v.x + v.y * v.y + v.z * v.z + v.w * v.w;
        ss += __shfl_xor_sync(0xffffffffu, ss, 1);
        ss += __shfl_xor_sync(0xffffffffu, ss, 2);
        ss += __shfl_xor_sync(0xffffffffu, ss, 4);
        ss += __shfl_xor_sync(0xffffffffu, ss, 8);
        float norm = sqrtf(ss) * 0.125f;
        float sc = 0.125f / fmaxf(norm, 1e-8f);
        v.x *= sc * g4.x; v.y *= sc * g4.y;
        v.z *= sc * g4.z; v.w *= sc * g4.w;
        *(float4*)(Ps + (p * 16 + sr) * PSS + c4) = v;
    }
    __syncthreads();

    unsigned qf[8][4];
#pragma unroll
    for (int c = 0; c < 8; c++) {
        qf[c][0] = f2tf32(Ps[r0 * PSS + c * 8 + tig]);
        qf[c][1] = f2tf32(Ps[(r0 + 8) * PSS + c * 8 + tig]);
        qf[c][2] = f2tf32(Ps[r0 * PSS + c * 8 + tig + 4]);
        qf[c][3] = f2tf32(Ps[(r0 + 8) * PSS + c * 8 + tig + 4]);
    }
    float mlq0 = mask_l[b * SL_ + q0 + r0];
    float mlq1 = mask_l[b * SL_ + q0 + r0 + 8];

    float m0 = -INFINITY, m1 = -INFINITY, l0 = 0.f, l1 = 0.f;
    float o[8][4];
#pragma unroll
    for (int i = 0; i < 8; i++)
#pragma unroll
        for (int j = 0; j < 4; j++) o[i][j] = 0.f;

    const float* Kg = kvb + (size_t)b * SKV_ * (2 * D_) + h * DH_;
    const float* Sg = kscl + (size_t)b * SKV_ * H_ + h;

    for (int kt = 0; kt < SKV_ / 64; kt++) {
        __syncthreads();
#pragma unroll
        for (int p = 0; p < 4; p++) {
            int t = kt * 64 + p * 16 + sr;
            const float* src = Kg + (size_t)t * (2 * D_) + c4;
            float4 kvv = *(const float4*)src;
            float4 vvv = *(const float4*)(src + D_);
            float sc = Sg[(size_t)t * H_];
            kvv.x = f2tf32f(kvv.x * sc * g4.x);
            kvv.y = f2tf32f(kvv.y * sc * g4.y);
            kvv.z = f2tf32f(kvv.z * sc * g4.z);
            kvv.w = f2tf32f(kvv.w * sc * g4.w);
            vvv.x = f2tf32f(vvv.x); vvv.y = f2tf32f(vvv.y);
            vvv.z = f2tf32f(vvv.z); vvv.w = f2tf32f(vvv.w);
            *(float4*)(Ks + (p * 16 + sr) * KSS + c4) = kvv;
            *(float4*)(Vs + (p * 16 + sr) * VSS + c4) = vvv;
        }
        if (tid < 64) {
            int t = kt * 64 + tid;
            Ms[tid] = (t < SX_) ? mask_x[b * SX_ + t] : mask_l[b * SL_ + t - SX_];
        }
        __syncthreads();

        float s[8][4];
#pragma unroll
        for (int i = 0; i < 8; i++) { s[i][0] = s[i][1] = s[i][2] = s[i][3] = 0.f; }
#pragma unroll
        for (int c = 0; c < 8; c++) {
#pragma unroll
            for (int ni = 0; ni < 8; ni++) {
                unsigned kb0 = __float_as_uint(Ks[(ni * 8 + grp) * KSS + c * 8 + tig]);
                unsigned kb1 = __float_as_uint(Ks[(ni * 8 + grp) * KSS + c * 8 + tig + 4]);
                mma_tf32(s[ni][0], s[ni][1], s[ni][2], s[ni][3],
                         qf[c][0], qf[c][1], qf[c][2], qf[c][3], kb0, kb1);
            }
        }

        float mx0 = m0, mx1 = m1;
#pragma unroll
        for (int ni = 0; ni < 8; ni++) {
            float mk0 = Ms[ni * 8 + tig * 2], mk1 = Ms[ni * 8 + tig * 2 + 1];
            s[ni][0] += (1.f - mk0 * mlq0) * NEGMIN;
            s[ni][1] += (1.f - mk1 * mlq0) * NEGMIN;
            s[ni][2] += (1.f - mk0 * mlq1) * NEGMIN;
            s[ni][3] += (1.f - mk1 * mlq1) * NEGMIN;
            mx0 = fmaxf(mx0, fmaxf(s[ni][0], s[ni][1]));
            mx1 = fmaxf(mx1, fmaxf(s[ni][2], s[ni][3]));
        }
        mx0 = fmaxf(mx0, __shfl_xor_sync(0xffffffffu, mx0, 1));
        mx0 = fmaxf(mx0, __shfl_xor_sync(0xffffffffu, mx0, 2));
        mx1 = fmaxf(mx1, __shfl_xor_sync(0xffffffffu, mx1, 1));
        mx1 = fmaxf(mx1, __shfl_xor_sync(0xffffffffu, mx1, 2));
        float sc0 = expf(m0 - mx0);
        float sc1 = expf(m1 - mx1);
        m0 = mx0; m1 = mx1;
        float rs0 = 0.f, rs1 = 0.f;
#pragma unroll
        for (int ni = 0; ni < 8; ni++) {
            float p0 = expf(s[ni][0] - m0), p1 = expf(s[ni][1] - m0);
            float p2 = expf(s[ni][2] - m1), p3 = expf(s[ni][3] - m1);
            rs0 += p0 + p1; rs1 += p2 + p3;
            *(float2*)(Ps + r0 * PSS + ni * 8 + tig * 2) =
                make_float2(f2tf32f(p0), f2tf32f(p1));
            *(float2*)(Ps + (r0 + 8) * PSS + ni * 8 + tig * 2) =
                make_float2(f2tf32f(p2), f2tf32f(p3));
        }
        rs0 += __shfl_xor_sync(0xffffffffu, rs0, 1);
        rs0 += __shfl_xor_sync(0xffffffffu, rs0, 2);
        rs1 += __shfl_xor_sync(0xffffffffu, rs1, 1);
        rs1 += __shfl_xor_sync(0xffffffffu, rs1, 2);
        l0 = l0 * sc0 + rs0;
        l1 = l1 * sc1 + rs1;
#pragma unroll
        for (int ni = 0; ni < 8; ni++) {
            o[ni][0] *= sc0; o[ni][1] *= sc0;
            o[ni][2] *= sc1; o[ni][3] *= sc1;
        }
        __syncwarp();

#pragma unroll
        for (int c = 0; c < 8; c++) {
            unsigned pf0 = __float_as_uint(Ps[r0 * PSS + c * 8 + tig]);
            unsigned pf1 = __float_as_uint(Ps[(r0 + 8) * PSS + c * 8 + tig]);
            unsigned pf2 = __float_as_uint(Ps[r0 * PSS + c * 8 + tig + 4]);
            unsigned pf3 = __float_as_uint(Ps[(r0 + 8) * PSS + c * 8 + tig + 4]);
#pragma unroll
            for (int ni = 0; ni < 8; ni++) {
                unsigned vb0 = __float_as_uint(Vs[(c * 8 + tig) * VSS + ni * 8 + grp]);
                unsigned vb1 = __float_as_uint(Vs[(c * 8 + tig + 4) * VSS + ni * 8 + grp]);
                mma_tf32(o[ni][0], o[ni][1], o[ni][2], o[ni][3],
                         pf0, pf1, pf2, pf3, vb0, vb1);
            }
        }
    }

    // y rounded to tf32 (consumed by the out-projection GEMM)
    float inv0 = 1.f / l0, inv1 = 1.f / l1;
    float* yg = y + ((size_t)b * SL_ + q0 + r0) * D_ + h * DH_;
#pragma unroll
    for (int ni = 0; ni < 8; ni++) {
        *(float2*)(yg + ni * 8 + tig * 2) =
            make_float2(f2tf32f(o[ni][0] * inv0), f2tf32f(o[ni][1] * inv0));
        *(float2*)(yg + (size_t)8 * D_ + ni * 8 + tig * 2) =
            make_float2(f2tf32f(o[ni][2] * inv1), f2tf32f(o[ni][3] * inv1));
    }
}

// ---------------- launch ----------------
extern "C" void kernel_launch(void* const* d_in, const int* in_sizes, int n_in,
                              void* d_out, int out_size)
{
    const float* x       = (const float*)d_in[0];
    const float* latents = (const float*)d_in[1];
    const float* mask_x  = (const float*)d_in[2];
    const float* mask_l  = (const float*)d_in[3];
    const float* ln_x_g  = (const float*)d_in[4];
    const float* ln_x_b  = (const float*)d_in[5];
    const float* ln_l_g  = (const float*)d_in[6];
    const float* ln_l_b  = (const float*)d_in[7];
    const float* Wq      = (const float*)d_in[8];
    const float* Wkv     = (const float*)d_in[9];
    const float* qk_g    = (const float*)d_in[10];
    const float* Wo      = (const float*)d_in[11];
    float* out = (float*)d_out;

    float *kvin, *lnb, *qb, *kvb, *yb, *wt, *ksb;
    cudaGetSymbolAddress((void**)&kvin, g_kvin);
    cudaGetSymbolAddress((void**)&lnb,  g_ln);
    cudaGetSymbolAddress((void**)&qb,   g_q);
    cudaGetSymbolAddress((void**)&kvb,  g_kv);
    cudaGetSymbolAddress((void**)&yb,   g_y);
    cudaGetSymbolAddress((void**)&wt,   g_wt);
    cudaGetSymbolAddress((void**)&ksb,  g_ks);
    float* wq32  = wt;
    float* wkv32 = wt + (size_t)1024 * 1024;
    float* wo32  = wt + (size_t)3 * 1024 * 1024;

    int flash_smem   = (64 * KSS + 64 * VSS + 128 * PSS + 64) * 4;
    int gemm_smem128 = 3 * (128 * AST + 16 * (128 + 8)) * 4;   // 56832
    int gemm_smem64  = 3 * (128 * AST + 16 * (64 + 8)) * 4;    // 44544
    static int smem_set = 0;
    if (!smem_set) {
        cudaFuncSetAttribute(flash_kernel,
                             cudaFuncAttributeMaxDynamicSharedMemorySize, flash_smem);
        cudaFuncSetAttribute(tgemm_ca<128>,
                             cudaFuncAttributeMaxDynamicSharedMemorySize, gemm_smem128);
        cudaFuncSetAttribute(tgemm_ca<64>,
                             cudaFuncAttributeMaxDynamicSharedMemorySize, gemm_smem64);
        smem_set = 1;
    }

    // 0) round all weights to tf32 (one launch)
    cvt3_kernel<<<4096, 256>>>(Wq, Wkv, Wo, wq32);

    // 1) LayerNorms -> kvin (concat) and lnb, tf32-rounded
    ln_kernel<<<B_ * SX_, 256>>>(x, ln_x_g, ln_x_b, kvin, nullptr, SX_, 0);
    ln_kernel<<<B_ * SL_, 256>>>(latents, ln_l_g, ln_l_b, kvin, lnb, SL_, SX_);

    // 2) q = ln @ Wq   (TN=64 -> 128 CTAs)
    tgemm_ca<64><<<dim3(16, 8), 256, gemm_smem64>>>(lnb, D_, wq32, D_, qb, D_);

    // 3) kv = kvin @ Wkv   (TN=128, proven)
    tgemm_ca<128><<<dim3(16, 136), 256, gemm_smem128>>>(kvin, D_, wkv32, 2 * D_, kvb, 2 * D_);

    // 4) k RMS scales (read-only pass)
    kscale_kernel<<<(B_ * SKV_ * H_) / 8, 256>>>(kvb, ksb);

    // 5) fused attention (q RMS + k scale + mask + softmax) -> y (tf32-rounded)
    flash_kernel<<<dim3(SL_ / 128, B_ * H_), 256, flash_smem>>>(
        qb, kvb, mask_x, mask_l, qk_g, ksb, yb);

    // 6) out = y @ Wo   (TN=64 -> 128 CTAs)
    tgemm_ca<64><<<dim3(16, 8), 256, gemm_smem64>>>(yb, D_, wo32, D_, out, D_);
}